// round 13
// baseline (speedup 1.0000x reference)
#include <cuda_runtime.h>
#include <cuda_bf16.h>

// ---------------- problem constants ----------------
#define BB     8
#define NN     4096
#define SS     1024          // NPOINT
#define KK     32            // NSAMPLE
#define INCH   64
#define C0     67            // 3 + 64
#define C1     64
#define C2     64
#define C3     128
#define MTOT   (BB*SS*KK)    // 262144
#define R2     0.04f
#define EPSBN  1e-5f

// ---------------- packed f32x2 helpers ----------------
#define PACK_F32X2(out, lo, hi) \
    asm("mov.b64 %0, {%1, %2};" : "=l"(out) : "f"(lo), "f"(hi))
#define UNPACK_F32X2(lo, hi, in) \
    asm("mov.b64 {%0, %1}, %2;" : "=f"(lo), "=f"(hi) : "l"(in))
#define ADD_F32X2(out, a, b) \
    asm("add.rn.f32x2 %0, %1, %2;" : "=l"(out) : "l"(a), "l"(b))
#define MUL_F32X2(out, a, b) \
    asm("mul.rn.f32x2 %0, %1, %2;" : "=l"(out) : "l"(a), "l"(b))
#define FMA_F32X2(out, a, b, c) \
    asm("fma.rn.f32x2 %0, %1, %2, %3;" : "=l"(out) : "l"(a), "l"(b), "l"(c))

// monotone float<->u32 order-preserving map (atomicMax/Min on floats of any sign)
__device__ __forceinline__ unsigned fenc(float f) {
    unsigned u = __float_as_uint(f);
    return (u >> 31) ? ~u : (u | 0x80000000u);
}
__device__ __forceinline__ float fdec(unsigned k) {
    return __uint_as_float((k >> 31) ? (k & 0x7fffffffu) : ~k);
}

// ---------------- scratch (__device__ globals; no allocations) ----------------
__device__ float g_newxyz[BB*SS*3];
__device__ float g_x0[MTOT*C0];
__device__ float g_y1[MTOT*C1];
__device__ float g_y2[MTOT*C2];
__device__ float g_pmax[BB*SS*C3];
__device__ float g_pmin[BB*SS*C3];
__device__ float g_sum[3*128];
__device__ float g_sqs[3*128];

// ---------------- FPS (block 0 also zeroes stats) ----------------
__global__ __launch_bounds__(1024, 1)
void fps_kernel(const float* __restrict__ xyz, float* __restrict__ newxyz, float* __restrict__ out_xyz) {
    const int b    = blockIdx.x;
    const int tid  = threadIdx.x;
    const int lane = tid & 31;
    const int warp = tid >> 5;

    if (b == 0 && tid < 3*128) { g_sum[tid] = 0.f; g_sqs[tid] = 0.f; }

    const float* base = xyz + b * NN * 3;

    float px[4], py[4], pz[4], dist[4];
#pragma unroll
    for (int p = 0; p < 4; p++) {
        int i = tid + p * 1024;
        px[p] = base[i*3+0]; py[p] = base[i*3+1]; pz[p] = base[i*3+2];
        dist[p] = 1e10f;
    }
    unsigned long long pxp[2], pyp[2], pzp[2];
#pragma unroll
    for (int q = 0; q < 2; q++) {
        PACK_F32X2(pxp[q], px[2*q], px[2*q+1]);
        PACK_F32X2(pyp[q], py[2*q], py[2*q+1]);
        PACK_F32X2(pzp[q], pz[2*q], pz[2*q+1]);
    }

    __shared__ unsigned s_val[2][32];
    __shared__ unsigned s_idx[2][32];
    __shared__ float4   s_c[2][32];          // negated centroid, one LDS.128

    float c0x = base[0], c0y = base[1], c0z = base[2];
    unsigned long long cnx, cny, cnz;
    {
        float nx = -c0x, ny = -c0y, nz = -c0z;
        PACK_F32X2(cnx, nx, nx);
        PACK_F32X2(cny, ny, ny);
        PACK_F32X2(cnz, nz, nz);
    }

    for (int s = 0; s < SS; s++) {
        if (tid == 0) {
            float lx, hx, ly, hy, lz, hz;
            UNPACK_F32X2(lx, hx, cnx);
            UNPACK_F32X2(ly, hy, cny);
            UNPACK_F32X2(lz, hz, cnz);
            int o = (b*SS + s) * 3;
            newxyz[o+0] = -lx; newxyz[o+1] = -ly; newxyz[o+2] = -lz;
            out_xyz[o+0] = -lx; out_xyz[o+1] = -ly; out_xyz[o+2] = -lz;
        }

        float nd[4];
#pragma unroll
        for (int q = 0; q < 2; q++) {
            unsigned long long dx, dy, dz, sx, sy, sz, s01, d2;
            ADD_F32X2(dx, pxp[q], cnx);      // p + (-c) == __fsub_rn(p, c) per half
            ADD_F32X2(dy, pyp[q], cny);
            ADD_F32X2(dz, pzp[q], cnz);
            MUL_F32X2(sx, dx, dx);
            MUL_F32X2(sy, dy, dy);
            MUL_F32X2(sz, dz, dz);
            ADD_F32X2(s01, sx, sy);
            ADD_F32X2(d2, s01, sz);
            float d0, d1;
            UNPACK_F32X2(d0, d1, d2);
            nd[2*q]   = fminf(dist[2*q],   d0);
            nd[2*q+1] = fminf(dist[2*q+1], d1);
            dist[2*q] = nd[2*q]; dist[2*q+1] = nd[2*q+1];
        }

        float bv = nd[0]; unsigned bi = (unsigned)tid;
        if (nd[1] > bv) { bv = nd[1]; bi = tid + 1024u; }
        if (nd[2] > bv) { bv = nd[2]; bi = tid + 2048u; }
        if (nd[3] > bv) { bv = nd[3]; bi = tid + 3072u; }

        unsigned vb   = __float_as_uint(bv);              // dist >= 0: bits order-preserving
        unsigned wmax = __reduce_max_sync(0xffffffffu, vb);
        unsigned cand = (vb == wmax) ? bi : 0xffffffffu;
        unsigned widx = __reduce_min_sync(0xffffffffu, cand);

        const int buf = s & 1;
        if (lane == (int)(widx & 31u)) {
            int p = (int)(widx >> 10);
            s_val[buf][warp] = wmax;
            s_idx[buf][warp] = widx;
            s_c[buf][warp]   = make_float4(-px[p], -py[p], -pz[p], 0.f);
        }
        __syncthreads();

        unsigned vv = s_val[buf][lane];
        unsigned gi = s_idx[buf][lane];
        unsigned gmax  = __reduce_max_sync(0xffffffffu, vv);
        unsigned cand2 = (vv == gmax) ? gi : 0xffffffffu;
        unsigned gwin  = __reduce_min_sync(0xffffffffu, cand2);
        int slot = (int)((gwin & 1023u) >> 5);    // owner warp of winning point
        float4 cc = s_c[buf][slot];
        PACK_F32X2(cnx, cc.x, cc.x);
        PACK_F32X2(cny, cc.y, cc.y);
        PACK_F32X2(cnz, cc.z, cc.z);
    }
}

// ---------------- ball query + gather + concat -> x0 [M, 67] ----------------
__global__ __launch_bounds__(128)
void ballgather_kernel(const float* __restrict__ xyz, const float* __restrict__ points,
                       const float* __restrict__ newxyz, float* __restrict__ x0) {
    extern __shared__ float sh[];
    float* sx = sh;
    float* sy = sh + NN;
    float* sz = sh + 2*NN;
    __shared__ int s_sel[4][32];

    const int b   = blockIdx.y;
    const int blk = blockIdx.x;
    const int tid = threadIdx.x;
    const int w    = tid >> 5;
    const int lane = tid & 31;

    const float* base = xyz + b * NN * 3;
    for (int i = tid; i < NN; i += 128) {
        sx[i] = base[i*3+0]; sy[i] = base[i*3+1]; sz[i] = base[i*3+2];
    }
    __syncthreads();

    const float* pb = points + b * NN * INCH;

    for (int qq = 0; qq < 8; qq++) {
        int s = blk * 32 + w * 8 + qq;
        int g = b * SS + s;
        float cx = newxyz[g*3+0], cy = newxyz[g*3+1], cz = newxyz[g*3+2];

        int cnt = 0;
        for (int j0 = 0; j0 < NN && cnt < KK; j0 += 32) {
            int j = j0 + lane;
            float dx = __fsub_rn(cx, sx[j]);
            float dy = __fsub_rn(cy, sy[j]);
            float dz = __fsub_rn(cz, sz[j]);
            float d  = __fadd_rn(__fadd_rn(__fmul_rn(dx,dx), __fmul_rn(dy,dy)), __fmul_rn(dz,dz));
            bool in = !(d > R2);
            unsigned m = __ballot_sync(0xffffffffu, in);
            if (in) {
                int slot = cnt + __popc(m & ((1u << lane) - 1u));
                if (slot < KK) s_sel[w][slot] = j;
            }
            cnt += __popc(m);
        }
        __syncwarp();
        if (cnt < KK) {
            int first = s_sel[w][0];
            if (lane >= cnt) s_sel[w][lane] = first;
        }
        __syncwarp();

        int idx = s_sel[w][lane];
        int rowbase = (g * KK + lane) * C0;
        x0[rowbase+0] = __fsub_rn(sx[idx], cx);
        x0[rowbase+1] = __fsub_rn(sy[idx], cy);
        x0[rowbase+2] = __fsub_rn(sz[idx], cz);
#pragma unroll 4
        for (int k = 0; k < KK; k++) {
            int id2 = __shfl_sync(0xffffffffu, idx, k);
            int rb = (g * KK + k) * C0 + 3;
            x0[rb + lane]      = pb[id2 * INCH + lane];
            x0[rb + 32 + lane] = pb[id2 * INCH + 32 + lane];
        }
    }
}

// ---------------- GEMM (FFMA2) + bias + fused BN-prep-in + stats + optional pool ----------
// BNIN: compute input-BN scale/shift from raw sums (insum/insqs/ing/inbt) in prologue.
template<int CIN, int COUT, int TN, bool BNIN, bool DUPW, bool POOL>
__global__ __launch_bounds__(256)
void gemm_bn_kernel(const float* __restrict__ X, const float* __restrict__ W,
                    const float* __restrict__ bias,
                    const float* __restrict__ insum, const float* __restrict__ insqs,
                    const float* __restrict__ ing, const float* __restrict__ inbt,
                    float* __restrict__ Y, float* __restrict__ osum, float* __restrict__ osqs,
                    float* __restrict__ pmax, float* __restrict__ pmin) {
    extern __shared__ float sh[];
    float* xT  = sh;                          // [CIN][130]
    float* wS  = sh + CIN * 130;              // DUPW: CIN*COUT float2 ; else [CIN][COUT+1]
    __shared__ float s_sum[COUT];
    __shared__ float s_sqs[COUT];
    __shared__ float s_scale[BNIN ? CIN : 1];
    __shared__ float s_shift[BNIN ? CIN : 1];
    __shared__ unsigned s_pmax[POOL ? 4*COUT : 1];
    __shared__ unsigned s_pmin[POOL ? 4*COUT : 1];

    const int tid = threadIdx.x;
    if (tid < COUT) { s_sum[tid] = 0.f; s_sqs[tid] = 0.f; }
    if (POOL) {
        for (int i = tid; i < 4*COUT; i += 256) { s_pmax[i] = 0u; s_pmin[i] = 0xffffffffu; }
    }
    if (BNIN) {
        if (tid < CIN) {
            const float inv = 1.0f / (float)MTOT;
            float mu  = insum[tid] * inv;
            float var = insqs[tid] * inv - mu * mu;
            float sc  = ing[tid] * rsqrtf(var + EPSBN);
            s_scale[tid] = sc;
            s_shift[tid] = fmaf(-mu, sc, inbt[tid]);
        }
        __syncthreads();
    }

    const int r0 = blockIdx.x * 128;

    if (DUPW) {
        float2* w2 = reinterpret_cast<float2*>(wS);
        for (int i = tid; i < CIN * COUT; i += 256) {
            int o = i / CIN, c = i - o * CIN;
            float w = W[i];
            w2[c * COUT + o] = make_float2(w, w);
        }
    } else {
        for (int i = tid; i < CIN * COUT; i += 256) {
            int o = i / CIN, c = i - o * CIN;
            wS[c * (COUT + 1) + o] = W[i];
        }
    }
    for (int i = tid; i < 128 * CIN; i += 256) {
        int r = i / CIN, c = i - r * CIN;
        float v = X[(r0 + r) * CIN + c];
        if (BNIN) v = fmaxf(fmaf(v, s_scale[c], s_shift[c]), 0.f);
        xT[c * 130 + r] = v;
    }
    __syncthreads();

    const int tx = tid & 15, ty = tid >> 4;
    unsigned long long acc2[4][TN];
#pragma unroll
    for (int j = 0; j < TN; j++) {
        float bj = bias[tx + 16 * j];
        unsigned long long bp;
        PACK_F32X2(bp, bj, bj);
#pragma unroll
        for (int ip = 0; ip < 4; ip++) acc2[ip][j] = bp;
    }

#pragma unroll 2
    for (int c = 0; c < CIN; c++) {
        unsigned long long xv2[4];
#pragma unroll
        for (int ip = 0; ip < 4; ip++)
            xv2[ip] = *reinterpret_cast<const unsigned long long*>(&xT[c * 130 + 2 * ty + 32 * ip]);
        unsigned long long wv2[TN];
#pragma unroll
        for (int j = 0; j < TN; j++) {
            if (DUPW) {
                wv2[j] = *reinterpret_cast<const unsigned long long*>(
                             &reinterpret_cast<float2*>(wS)[c * COUT + tx + 16 * j]);
            } else {
                float wv = wS[c * (COUT + 1) + tx + 16 * j];
                PACK_F32X2(wv2[j], wv, wv);
            }
        }
#pragma unroll
        for (int ip = 0; ip < 4; ip++)
#pragma unroll
            for (int j = 0; j < TN; j++)
                FMA_F32X2(acc2[ip][j], xv2[ip], wv2[j], acc2[ip][j]);
    }

    float ls[TN], lq[TN];
#pragma unroll
    for (int j = 0; j < TN; j++) { ls[j] = 0.f; lq[j] = 0.f; }
#pragma unroll
    for (int ip = 0; ip < 4; ip++) {
        int row = r0 + 2 * ty + 32 * ip;
#pragma unroll
        for (int j = 0; j < TN; j++) {
            float v0, v1;
            UNPACK_F32X2(v0, v1, acc2[ip][j]);
            int col = tx + 16 * j;
            if (!POOL) {
                Y[row * COUT + col]       = v0;
                Y[(row + 1) * COUT + col] = v1;
            } else {
                float mx = fmaxf(v0, v1), mn = fminf(v0, v1);
                float omx = __shfl_xor_sync(0xffffffffu, mx, 16);
                float omn = __shfl_xor_sync(0xffffffffu, mn, 16);
                mx = fmaxf(mx, omx); mn = fminf(mn, omn);
                if (!(tid & 16)) {
                    atomicMax(&s_pmax[ip * COUT + col], fenc(mx));
                    atomicMin(&s_pmin[ip * COUT + col], fenc(mn));
                }
            }
            ls[j] += v0 + v1;
            lq[j] += v0 * v0 + v1 * v1;
        }
    }
#pragma unroll
    for (int j = 0; j < TN; j++) {
        atomicAdd(&s_sum[tx + 16 * j], ls[j]);
        atomicAdd(&s_sqs[tx + 16 * j], lq[j]);
    }
    __syncthreads();
    if (tid < COUT) {
        atomicAdd(&osum[tid], s_sum[tid]);
        atomicAdd(&osqs[tid], s_sqs[tid]);
    }
    if (POOL) {
        for (int i = tid; i < 4*COUT; i += 256) {
            int g = blockIdx.x * 4 + i / COUT;
            int c = i - (i / COUT) * COUT;
            pmax[g * COUT + c] = fdec(s_pmax[i]);
            pmin[g * COUT + c] = fdec(s_pmin[i]);
        }
    }
}

// ---------------- finalize: layer-3 BN from stats, pick max/min by sign, relu ----------
// relu(fma(v,sc,sf)) is monotone in v (direction = sign(sc)), so pooling max/min
// pre-BN and selecting by sign is bit-exact vs pooling post-BN-ReLU.
__global__ __launch_bounds__(128)
void pool_finalize_kernel(const float* __restrict__ pmax, const float* __restrict__ pmin,
                          const float* __restrict__ sum, const float* __restrict__ sqs,
                          const float* __restrict__ g, const float* __restrict__ bt,
                          float* __restrict__ out) {
    int gidx = blockIdx.x;
    int o = threadIdx.x;
    const float inv = 1.0f / (float)MTOT;
    float mu  = sum[o] * inv;
    float var = sqs[o] * inv - mu * mu;
    float sc  = g[o] * rsqrtf(var + EPSBN);
    float sf  = fmaf(-mu, sc, bt[o]);
    float v = (sc >= 0.f) ? pmax[gidx * C3 + o] : pmin[gidx * C3 + o];
    out[BB * SS * 3 + gidx * C3 + o] = fmaxf(fmaf(v, sc, sf), 0.f);
}

// ---------------- host launcher ----------------
extern "C" void kernel_launch(void* const* d_in, const int* in_sizes, int n_in,
                              void* d_out, int out_size) {
    const float* xyz    = (const float*)d_in[0];
    const float* points = (const float*)d_in[1];
    const float* w0 = (const float*)d_in[2];
    const float* b0 = (const float*)d_in[3];
    const float* gg0 = (const float*)d_in[4];
    const float* bt0 = (const float*)d_in[5];
    const float* w1 = (const float*)d_in[6];
    const float* b1 = (const float*)d_in[7];
    const float* gg1 = (const float*)d_in[8];
    const float* bt1 = (const float*)d_in[9];
    const float* w2 = (const float*)d_in[10];
    const float* b2 = (const float*)d_in[11];
    const float* gg2 = (const float*)d_in[12];
    const float* bt2 = (const float*)d_in[13];
    float* out = (float*)d_out;

    float *p_newxyz, *p_x0, *p_y1, *p_y2, *p_pmax, *p_pmin, *p_sum, *p_sqs;
    cudaGetSymbolAddress((void**)&p_newxyz, g_newxyz);
    cudaGetSymbolAddress((void**)&p_x0, g_x0);
    cudaGetSymbolAddress((void**)&p_y1, g_y1);
    cudaGetSymbolAddress((void**)&p_y2, g_y2);
    cudaGetSymbolAddress((void**)&p_pmax, g_pmax);
    cudaGetSymbolAddress((void**)&p_pmin, g_pmin);
    cudaGetSymbolAddress((void**)&p_sum, g_sum);
    cudaGetSymbolAddress((void**)&p_sqs, g_sqs);

    const size_t sm_ball  = (size_t)3 * NN * 4;                        // 48 KB
    const size_t sm_gemm1 = (size_t)(C0 * 130 + C0 * C1 * 2) * 4;      // 69,144 B
    const size_t sm_gemm2 = (size_t)(C1 * 130 + C1 * C2 * 2) * 4;      // 66,048 B
    const size_t sm_gemm3 = (size_t)(C2 * 130 + C2 * (C3 + 1)) * 4;    // 66,304 B

    cudaFuncSetAttribute(ballgather_kernel,
                         cudaFuncAttributeMaxDynamicSharedMemorySize, (int)sm_ball);
    cudaFuncSetAttribute(gemm_bn_kernel<C0, C1, 4, false, true, false>,
                         cudaFuncAttributeMaxDynamicSharedMemorySize, (int)sm_gemm1);
    cudaFuncSetAttribute(gemm_bn_kernel<C1, C2, 4, true, true, false>,
                         cudaFuncAttributeMaxDynamicSharedMemorySize, (int)sm_gemm2);
    cudaFuncSetAttribute(gemm_bn_kernel<C2, C3, 8, true, false, true>,
                         cudaFuncAttributeMaxDynamicSharedMemorySize, (int)sm_gemm3);

    fps_kernel<<<BB, 1024>>>(xyz, p_newxyz, out);    // also zeroes stats (block 0)
    ballgather_kernel<<<dim3(32, BB), 128, sm_ball>>>(xyz, points, p_newxyz, p_x0);

    gemm_bn_kernel<C0, C1, 4, false, true, false><<<MTOT / 128, 256, sm_gemm1>>>(
        p_x0, w0, b0, nullptr, nullptr, nullptr, nullptr,
        p_y1, p_sum + 0, p_sqs + 0, nullptr, nullptr);

    gemm_bn_kernel<C1, C2, 4, true, true, false><<<MTOT / 128, 256, sm_gemm2>>>(
        p_y1, w1, b1, p_sum + 0, p_sqs + 0, gg0, bt0,
        p_y2, p_sum + 128, p_sqs + 128, nullptr, nullptr);

    gemm_bn_kernel<C2, C3, 8, true, false, true><<<MTOT / 128, 256, sm_gemm3>>>(
        p_y2, w2, b2, p_sum + 128, p_sqs + 128, gg1, bt1,
        nullptr, p_sum + 256, p_sqs + 256, p_pmax, p_pmin);

    pool_finalize_kernel<<<BB * SS, 128>>>(p_pmax, p_pmin,
        p_sum + 256, p_sqs + 256, gg2, bt2, out);
}

// round 16
// speedup vs baseline: 1.6869x; 1.6869x over previous
#include <cuda_runtime.h>
#include <cuda_bf16.h>

// ---------------- problem constants ----------------
#define BB     8
#define NN     4096
#define SS     1024          // NPOINT
#define KK     32            // NSAMPLE
#define INCH   64
#define C0     67            // 3 + 64
#define C1     64
#define C2     64
#define C3     128
#define MTOT   (BB*SS*KK)    // 262144
#define R2     0.04f
#define EPSBN  1e-5f

// ---------------- packed f32x2 helpers ----------------
#define PACK_F32X2(out, lo, hi) \
    asm("mov.b64 %0, {%1, %2};" : "=l"(out) : "f"(lo), "f"(hi))
#define UNPACK_F32X2(lo, hi, in) \
    asm("mov.b64 {%0, %1}, %2;" : "=f"(lo), "=f"(hi) : "l"(in))
#define ADD_F32X2(out, a, b) \
    asm("add.rn.f32x2 %0, %1, %2;" : "=l"(out) : "l"(a), "l"(b))
#define MUL_F32X2(out, a, b) \
    asm("mul.rn.f32x2 %0, %1, %2;" : "=l"(out) : "l"(a), "l"(b))
#define FMA_F32X2(out, a, b, c) \
    asm("fma.rn.f32x2 %0, %1, %2, %3;" : "=l"(out) : "l"(a), "l"(b), "l"(c))

// monotone float<->u32 order-preserving map (atomicMax/Min on floats of any sign)
__device__ __forceinline__ unsigned fenc(float f) {
    unsigned u = __float_as_uint(f);
    return (u >> 31) ? ~u : (u | 0x80000000u);
}
__device__ __forceinline__ float fdec(unsigned k) {
    return __uint_as_float((k >> 31) ? (k & 0x7fffffffu) : ~k);
}

// ---------------- scratch (__device__ globals; no allocations) ----------------
__device__ float g_newxyz[BB*SS*3];
__device__ float g_x0[MTOT*C0];
__device__ float g_y1[MTOT*C1];
__device__ float g_y2[MTOT*C2];
__device__ float g_pmax[BB*SS*C3];
__device__ float g_pmin[BB*SS*C3];
__device__ float g_sum[3*128];
__device__ float g_sqs[3*128];
__device__ float g_scale[3*128];
__device__ float g_shift[3*128];

// ---------------- FPS (block 0 also zeroes stats) ----------------
__global__ __launch_bounds__(1024, 1)
void fps_kernel(const float* __restrict__ xyz, float* __restrict__ newxyz, float* __restrict__ out_xyz) {
    const int b    = blockIdx.x;
    const int tid  = threadIdx.x;
    const int lane = tid & 31;
    const int warp = tid >> 5;

    if (b == 0 && tid < 3*128) { g_sum[tid] = 0.f; g_sqs[tid] = 0.f; }

    const float* base = xyz + b * NN * 3;

    float px[4], py[4], pz[4], dist[4];
#pragma unroll
    for (int p = 0; p < 4; p++) {
        int i = tid + p * 1024;
        px[p] = base[i*3+0]; py[p] = base[i*3+1]; pz[p] = base[i*3+2];
        dist[p] = 1e10f;
    }
    unsigned long long pxp[2], pyp[2], pzp[2];
#pragma unroll
    for (int q = 0; q < 2; q++) {
        PACK_F32X2(pxp[q], px[2*q], px[2*q+1]);
        PACK_F32X2(pyp[q], py[2*q], py[2*q+1]);
        PACK_F32X2(pzp[q], pz[2*q], pz[2*q+1]);
    }

    __shared__ unsigned s_val[2][32];
    __shared__ unsigned s_idx[2][32];
    __shared__ float4   s_c[2][32];          // negated centroid, one LDS.128

    float c0x = base[0], c0y = base[1], c0z = base[2];
    unsigned long long cnx, cny, cnz;
    {
        float nx = -c0x, ny = -c0y, nz = -c0z;
        PACK_F32X2(cnx, nx, nx);
        PACK_F32X2(cny, ny, ny);
        PACK_F32X2(cnz, nz, nz);
    }

    for (int s = 0; s < SS; s++) {
        if (tid == 0) {
            float lx, hx, ly, hy, lz, hz;
            UNPACK_F32X2(lx, hx, cnx);
            UNPACK_F32X2(ly, hy, cny);
            UNPACK_F32X2(lz, hz, cnz);
            int o = (b*SS + s) * 3;
            newxyz[o+0] = -lx; newxyz[o+1] = -ly; newxyz[o+2] = -lz;
            out_xyz[o+0] = -lx; out_xyz[o+1] = -ly; out_xyz[o+2] = -lz;
        }

        float nd[4];
#pragma unroll
        for (int q = 0; q < 2; q++) {
            unsigned long long dx, dy, dz, sx, sy, sz, s01, d2;
            ADD_F32X2(dx, pxp[q], cnx);      // p + (-c) == __fsub_rn(p, c) per half
            ADD_F32X2(dy, pyp[q], cny);
            ADD_F32X2(dz, pzp[q], cnz);
            MUL_F32X2(sx, dx, dx);
            MUL_F32X2(sy, dy, dy);
            MUL_F32X2(sz, dz, dz);
            ADD_F32X2(s01, sx, sy);
            ADD_F32X2(d2, s01, sz);
            float d0, d1;
            UNPACK_F32X2(d0, d1, d2);
            nd[2*q]   = fminf(dist[2*q],   d0);
            nd[2*q+1] = fminf(dist[2*q+1], d1);
            dist[2*q] = nd[2*q]; dist[2*q+1] = nd[2*q+1];
        }

        float bv = nd[0]; unsigned bi = (unsigned)tid;
        if (nd[1] > bv) { bv = nd[1]; bi = tid + 1024u; }
        if (nd[2] > bv) { bv = nd[2]; bi = tid + 2048u; }
        if (nd[3] > bv) { bv = nd[3]; bi = tid + 3072u; }

        unsigned vb   = __float_as_uint(bv);              // dist >= 0: bits order-preserving
        unsigned wmax = __reduce_max_sync(0xffffffffu, vb);
        unsigned cand = (vb == wmax) ? bi : 0xffffffffu;
        unsigned widx = __reduce_min_sync(0xffffffffu, cand);

        const int buf = s & 1;
        if (lane == (int)(widx & 31u)) {
            int p = (int)(widx >> 10);
            s_val[buf][warp] = wmax;
            s_idx[buf][warp] = widx;
            s_c[buf][warp]   = make_float4(-px[p], -py[p], -pz[p], 0.f);
        }
        __syncthreads();

        unsigned vv = s_val[buf][lane];
        unsigned gi = s_idx[buf][lane];
        unsigned gmax  = __reduce_max_sync(0xffffffffu, vv);
        unsigned cand2 = (vv == gmax) ? gi : 0xffffffffu;
        unsigned gwin  = __reduce_min_sync(0xffffffffu, cand2);
        int slot = (int)((gwin & 1023u) >> 5);    // owner warp of winning point
        float4 cc = s_c[buf][slot];
        PACK_F32X2(cnx, cc.x, cc.x);
        PACK_F32X2(cny, cc.y, cc.y);
        PACK_F32X2(cnz, cc.z, cc.z);
    }
}

// ---------------- ball query + gather + concat -> x0 [M, 67] ----------------
__global__ __launch_bounds__(128)
void ballgather_kernel(const float* __restrict__ xyz, const float* __restrict__ points,
                       const float* __restrict__ newxyz, float* __restrict__ x0) {
    extern __shared__ float sh[];
    float* sx = sh;
    float* sy = sh + NN;
    float* sz = sh + 2*NN;
    __shared__ int s_sel[4][32];

    const int b   = blockIdx.y;
    const int blk = blockIdx.x;
    const int tid = threadIdx.x;
    const int w    = tid >> 5;
    const int lane = tid & 31;

    const float* base = xyz + b * NN * 3;
    for (int i = tid; i < NN; i += 128) {
        sx[i] = base[i*3+0]; sy[i] = base[i*3+1]; sz[i] = base[i*3+2];
    }
    __syncthreads();

    const float* pb = points + b * NN * INCH;

    for (int qq = 0; qq < 8; qq++) {
        int s = blk * 32 + w * 8 + qq;
        int g = b * SS + s;
        float cx = newxyz[g*3+0], cy = newxyz[g*3+1], cz = newxyz[g*3+2];

        int cnt = 0;
        for (int j0 = 0; j0 < NN && cnt < KK; j0 += 32) {
            int j = j0 + lane;
            float dx = __fsub_rn(cx, sx[j]);
            float dy = __fsub_rn(cy, sy[j]);
            float dz = __fsub_rn(cz, sz[j]);
            float d  = __fadd_rn(__fadd_rn(__fmul_rn(dx,dx), __fmul_rn(dy,dy)), __fmul_rn(dz,dz));
            bool in = !(d > R2);
            unsigned m = __ballot_sync(0xffffffffu, in);
            if (in) {
                int slot = cnt + __popc(m & ((1u << lane) - 1u));
                if (slot < KK) s_sel[w][slot] = j;
            }
            cnt += __popc(m);
        }
        __syncwarp();
        if (cnt < KK) {
            int first = s_sel[w][0];
            if (lane >= cnt) s_sel[w][lane] = first;
        }
        __syncwarp();

        int idx = s_sel[w][lane];
        int rowbase = (g * KK + lane) * C0;
        x0[rowbase+0] = __fsub_rn(sx[idx], cx);
        x0[rowbase+1] = __fsub_rn(sy[idx], cy);
        x0[rowbase+2] = __fsub_rn(sz[idx], cz);
#pragma unroll 4
        for (int k = 0; k < KK; k++) {
            int id2 = __shfl_sync(0xffffffffu, idx, k);
            int rb = (g * KK + k) * C0 + 3;
            x0[rb + lane]      = pb[id2 * INCH + lane];
            x0[rb + 32 + lane] = pb[id2 * INCH + 32 + lane];
        }
    }
}

// ---------------- GEMM (FFMA2) + bias + optional BN-in + stats + optional fused pool ----
// X:[M,CIN], W:[COUT,CIN], Y:[M,COUT]. BM=128, 256 thr (16x16).
// Thread tile: 4 adjacent-row pairs (rows 2*ty+32*ip+{0,1}) x TN cols (tx+16*j).
// Non-DUPW only: wT [CIN][COUT+1], ~50-52KB smem -> 4 CTAs/SM (measured best config).
// POOL: don't store Y; per-group (32 rows) max/min reduced + written to pmax/pmin.
template<int CIN, int COUT, int TN, bool BNIN, bool POOL>
__global__ __launch_bounds__(256)
void gemm_bn_kernel(const float* __restrict__ X, const float* __restrict__ W,
                    const float* __restrict__ bias,
                    const float* __restrict__ scale, const float* __restrict__ shift,
                    float* __restrict__ Y, float* __restrict__ osum, float* __restrict__ osqs,
                    float* __restrict__ pmax, float* __restrict__ pmin) {
    extern __shared__ float sh[];
    float* xT  = sh;                          // [CIN][130]
    float* wT  = sh + CIN * 130;              // [CIN][COUT+1]
    __shared__ float s_sum[COUT];
    __shared__ float s_sqs[COUT];
    __shared__ unsigned s_pmax[POOL ? 4*COUT : 1];
    __shared__ unsigned s_pmin[POOL ? 4*COUT : 1];

    const int tid = threadIdx.x;
    if (tid < COUT) { s_sum[tid] = 0.f; s_sqs[tid] = 0.f; }
    if (POOL) {
        for (int i = tid; i < 4*COUT; i += 256) { s_pmax[i] = 0u; s_pmin[i] = 0xffffffffu; }
    }

    const int r0 = blockIdx.x * 128;

    for (int i = tid; i < CIN * COUT; i += 256) {
        int o = i / CIN, c = i - o * CIN;
        wT[c * (COUT + 1) + o] = W[i];
    }
    for (int i = tid; i < 128 * CIN; i += 256) {
        int r = i / CIN, c = i - r * CIN;
        float v = X[(r0 + r) * CIN + c];
        if (BNIN) v = fmaxf(fmaf(v, scale[c], shift[c]), 0.f);
        xT[c * 130 + r] = v;
    }
    __syncthreads();

    const int tx = tid & 15, ty = tid >> 4;
    unsigned long long acc2[4][TN];
#pragma unroll
    for (int j = 0; j < TN; j++) {
        float bj = bias[tx + 16 * j];
        unsigned long long bp;
        PACK_F32X2(bp, bj, bj);
#pragma unroll
        for (int ip = 0; ip < 4; ip++) acc2[ip][j] = bp;
    }

#pragma unroll 2
    for (int c = 0; c < CIN; c++) {
        unsigned long long xv2[4];
#pragma unroll
        for (int ip = 0; ip < 4; ip++)
            xv2[ip] = *reinterpret_cast<const unsigned long long*>(&xT[c * 130 + 2 * ty + 32 * ip]);
        unsigned long long wv2[TN];
#pragma unroll
        for (int j = 0; j < TN; j++) {
            float wv = wT[c * (COUT + 1) + tx + 16 * j];
            PACK_F32X2(wv2[j], wv, wv);
        }
#pragma unroll
        for (int ip = 0; ip < 4; ip++)
#pragma unroll
            for (int j = 0; j < TN; j++)
                FMA_F32X2(acc2[ip][j], xv2[ip], wv2[j], acc2[ip][j]);
    }

    float ls[TN], lq[TN];
#pragma unroll
    for (int j = 0; j < TN; j++) { ls[j] = 0.f; lq[j] = 0.f; }
#pragma unroll
    for (int ip = 0; ip < 4; ip++) {
        int row = r0 + 2 * ty + 32 * ip;
#pragma unroll
        for (int j = 0; j < TN; j++) {
            float v0, v1;
            UNPACK_F32X2(v0, v1, acc2[ip][j]);
            int col = tx + 16 * j;
            if (!POOL) {
                Y[row * COUT + col]       = v0;
                Y[(row + 1) * COUT + col] = v1;
            } else {
                float mx = fmaxf(v0, v1), mn = fminf(v0, v1);
                float omx = __shfl_xor_sync(0xffffffffu, mx, 16);
                float omn = __shfl_xor_sync(0xffffffffu, mn, 16);
                mx = fmaxf(mx, omx); mn = fminf(mn, omn);
                if (!(tid & 16)) {
                    atomicMax(&s_pmax[ip * COUT + col], fenc(mx));
                    atomicMin(&s_pmin[ip * COUT + col], fenc(mn));
                }
            }
            ls[j] += v0 + v1;
            lq[j] += v0 * v0 + v1 * v1;
        }
    }
#pragma unroll
    for (int j = 0; j < TN; j++) {
        atomicAdd(&s_sum[tx + 16 * j], ls[j]);
        atomicAdd(&s_sqs[tx + 16 * j], lq[j]);
    }
    __syncthreads();
    if (tid < COUT) {
        atomicAdd(&osum[tid], s_sum[tid]);
        atomicAdd(&osqs[tid], s_sqs[tid]);
    }
    if (POOL) {
        for (int i = tid; i < 4*COUT; i += 256) {
            int g = blockIdx.x * 4 + i / COUT;
            int c = i - (i / COUT) * COUT;
            pmax[g * COUT + c] = fdec(s_pmax[i]);
            pmin[g * COUT + c] = fdec(s_pmin[i]);
        }
    }
}

// ---------------- BN param prep ----------------
__global__ void bnprep_kernel(const float* __restrict__ sum, const float* __restrict__ sqs,
                              const float* __restrict__ g, const float* __restrict__ bt,
                              float* __restrict__ scale, float* __restrict__ shift, int C) {
    int o = threadIdx.x;
    if (o < C) {
        const float inv = 1.0f / (float)MTOT;
        float mu  = sum[o] * inv;
        float var = sqs[o] * inv - mu * mu;
        float sc  = g[o] * rsqrtf(var + EPSBN);
        scale[o] = sc;
        shift[o] = fmaf(-mu, sc, bt[o]);
    }
}

// ---------------- finalize: pick max/min by sign(scale), BN+ReLU ----------------
// relu(fma(v,sc,sf)) is monotone in v (direction = sign(sc)), so pooling max/min
// pre-BN and selecting by sign is bit-exact vs pooling post-BN-ReLU.
__global__ __launch_bounds__(128)
void pool_finalize_kernel(const float* __restrict__ pmax, const float* __restrict__ pmin,
                          const float* __restrict__ scale, const float* __restrict__ shift,
                          float* __restrict__ out) {
    int gidx = blockIdx.x;
    int o = threadIdx.x;
    float sc = scale[o], sf = shift[o];
    float v = (sc >= 0.f) ? pmax[gidx * C3 + o] : pmin[gidx * C3 + o];
    out[BB * SS * 3 + gidx * C3 + o] = fmaxf(fmaf(v, sc, sf), 0.f);
}

// ---------------- host launcher ----------------
extern "C" void kernel_launch(void* const* d_in, const int* in_sizes, int n_in,
                              void* d_out, int out_size) {
    const float* xyz    = (const float*)d_in[0];
    const float* points = (const float*)d_in[1];
    const float* w0 = (const float*)d_in[2];
    const float* b0 = (const float*)d_in[3];
    const float* gg0 = (const float*)d_in[4];
    const float* bt0 = (const float*)d_in[5];
    const float* w1 = (const float*)d_in[6];
    const float* b1 = (const float*)d_in[7];
    const float* gg1 = (const float*)d_in[8];
    const float* bt1 = (const float*)d_in[9];
    const float* w2 = (const float*)d_in[10];
    const float* b2 = (const float*)d_in[11];
    const float* gg2 = (const float*)d_in[12];
    const float* bt2 = (const float*)d_in[13];
    float* out = (float*)d_out;

    float *p_newxyz, *p_x0, *p_y1, *p_y2, *p_pmax, *p_pmin, *p_sum, *p_sqs, *p_scale, *p_shift;
    cudaGetSymbolAddress((void**)&p_newxyz, g_newxyz);
    cudaGetSymbolAddress((void**)&p_x0, g_x0);
    cudaGetSymbolAddress((void**)&p_y1, g_y1);
    cudaGetSymbolAddress((void**)&p_y2, g_y2);
    cudaGetSymbolAddress((void**)&p_pmax, g_pmax);
    cudaGetSymbolAddress((void**)&p_pmin, g_pmin);
    cudaGetSymbolAddress((void**)&p_sum, g_sum);
    cudaGetSymbolAddress((void**)&p_sqs, g_sqs);
    cudaGetSymbolAddress((void**)&p_scale, g_scale);
    cudaGetSymbolAddress((void**)&p_shift, g_shift);

    const size_t sm_ball  = (size_t)3 * NN * 4;                        // 48 KB
    const size_t sm_gemm1 = (size_t)(C0 * 130 + C0 * (C1 + 1)) * 4;    // 52,260 B -> 4 CTAs
    const size_t sm_gemm2 = (size_t)(C1 * 130 + C1 * (C2 + 1)) * 4;    // 49,920 B -> 4 CTAs
    const size_t sm_gemm3 = (size_t)(C2 * 130 + C2 * (C3 + 1)) * 4;    // 66,304 B -> 3 CTAs

    cudaFuncSetAttribute(ballgather_kernel,
                         cudaFuncAttributeMaxDynamicSharedMemorySize, (int)sm_ball);
    cudaFuncSetAttribute(gemm_bn_kernel<C0, C1, 4, false, false>,
                         cudaFuncAttributeMaxDynamicSharedMemorySize, (int)sm_gemm1);
    cudaFuncSetAttribute(gemm_bn_kernel<C1, C2, 4, true, false>,
                         cudaFuncAttributeMaxDynamicSharedMemorySize, (int)sm_gemm2);
    cudaFuncSetAttribute(gemm_bn_kernel<C2, C3, 8, true, true>,
                         cudaFuncAttributeMaxDynamicSharedMemorySize, (int)sm_gemm3);

    fps_kernel<<<BB, 1024>>>(xyz, p_newxyz, out);    // also zeroes stats (block 0)
    ballgather_kernel<<<dim3(32, BB), 128, sm_ball>>>(xyz, points, p_newxyz, p_x0);

    gemm_bn_kernel<C0, C1, 4, false, false><<<MTOT / 128, 256, sm_gemm1>>>(
        p_x0, w0, b0, nullptr, nullptr, p_y1, p_sum + 0, p_sqs + 0, nullptr, nullptr);
    bnprep_kernel<<<1, 64>>>(p_sum + 0, p_sqs + 0, gg0, bt0, p_scale + 0, p_shift + 0, C1);

    gemm_bn_kernel<C1, C2, 4, true, false><<<MTOT / 128, 256, sm_gemm2>>>(
        p_y1, w1, b1, p_scale + 0, p_shift + 0, p_y2, p_sum + 128, p_sqs + 128, nullptr, nullptr);
    bnprep_kernel<<<1, 64>>>(p_sum + 128, p_sqs + 128, gg1, bt1, p_scale + 128, p_shift + 128, C2);

    gemm_bn_kernel<C2, C3, 8, true, true><<<MTOT / 128, 256, sm_gemm3>>>(
        p_y2, w2, b2, p_scale + 128, p_shift + 128, nullptr, p_sum + 256, p_sqs + 256,
        p_pmax, p_pmin);
    bnprep_kernel<<<1, 128>>>(p_sum + 256, p_sqs + 256, gg2, bt2, p_scale + 256, p_shift + 256, C3);

    pool_finalize_kernel<<<BB * SS, 128>>>(p_pmax, p_pmin, p_scale + 256, p_shift + 256, out);
}